// round 5
// baseline (speedup 1.0000x reference)
#include <cuda_runtime.h>
#include <cstdint>

// Scratch UV table: 512 floats per node (U = emb@W1_top + b1 in cols [0,256),
// V = emb@W1_bot in cols [256,512)). 131072 rows * 2KB = 268 MB.
#define UV_MAX_ROWS 131072
__device__ float g_uv[(size_t)UV_MAX_ROWS * 512];

// ---------------------------------------------------------------------------
// Kernel 1: UV precompute GEMM.  C[M,512] = A[M,128] @ B[128,512] (+ b1 fold)
//   B[k, j]      = W1[k*256 + j]          for j <  256   (W1_top)
//   B[k, 256+j]  = W1[(128+k)*256 + j]    for j >= 256   (W1_bot)
// Tiles: BM=128, BN=128, BK=16, 256 threads, 8x8 per thread, double-buffered.
// ---------------------------------------------------------------------------
__global__ __launch_bounds__(256)
void uv_gemm_kernel(const float* __restrict__ A,
                    const float* __restrict__ W1,
                    const float* __restrict__ b1,
                    int M)
{
    __shared__ float As[2][16][128];   // [buf][k][m]  (A stored transposed)
    __shared__ float Bs[2][16][128];   // [buf][k][n]

    const int tid = threadIdx.x;
    const int m0  = blockIdx.y * 128;
    const int n0  = blockIdx.x * 128;          // 0,128,256,384
    const float* Wb  = W1 + (n0 >= 256 ? 128 * 256 : 0);
    const int    nc0 = n0 & 255;               // 0 or 128

    const int tx = tid & 15;                   // 0..15  (n direction)
    const int ty = tid >> 4;                   // 0..15  (m direction)

    // A-load geometry: thread -> row (tid>>1), 8 consecutive floats at col (tid&1)*8
    const int a_row = tid >> 1;
    const int a_cb  = (tid & 1) * 8;
    const bool a_valid = (m0 + a_row) < M;
    const float* a_ptr = A + (size_t)(m0 + a_row) * 128 + a_cb;

    // B-load geometry: thread -> row (tid>>4), 8 consecutive floats at col (tid&15)*8
    const int b_row = tid >> 4;
    const int b_cb  = (tid & 15) * 8;
    const float* b_ptr = Wb + (size_t)b_row * 256 + nc0 + b_cb;

    float acc[8][8];
    #pragma unroll
    for (int i = 0; i < 8; i++)
        #pragma unroll
        for (int j = 0; j < 8; j++) acc[i][j] = 0.f;

    float4 ra0, ra1, rb0, rb1;
    const float4 z4 = make_float4(0.f, 0.f, 0.f, 0.f);

    // ---- prologue: load k-tile 0 ----
    ra0 = a_valid ? *(const float4*)(a_ptr)     : z4;
    ra1 = a_valid ? *(const float4*)(a_ptr + 4) : z4;
    rb0 = *(const float4*)(b_ptr);
    rb1 = *(const float4*)(b_ptr + 4);

    {   // store tile 0 into buf 0
        As[0][a_cb + 0][a_row] = ra0.x;  As[0][a_cb + 1][a_row] = ra0.y;
        As[0][a_cb + 2][a_row] = ra0.z;  As[0][a_cb + 3][a_row] = ra0.w;
        As[0][a_cb + 4][a_row] = ra1.x;  As[0][a_cb + 5][a_row] = ra1.y;
        As[0][a_cb + 6][a_row] = ra1.z;  As[0][a_cb + 7][a_row] = ra1.w;
        *(float4*)&Bs[0][b_row][b_cb]     = rb0;
        *(float4*)&Bs[0][b_row][b_cb + 4] = rb1;
    }
    __syncthreads();

    int buf = 0;
    #pragma unroll 1
    for (int t = 0; t < 8; t++) {           // 8 k-tiles of 16 (K=128)
        if (t < 7) {
            const int k0 = (t + 1) * 16;
            ra0 = a_valid ? *(const float4*)(a_ptr + k0)     : z4;
            ra1 = a_valid ? *(const float4*)(a_ptr + k0 + 4) : z4;
            rb0 = *(const float4*)(b_ptr + (size_t)k0 * 256);
            rb1 = *(const float4*)(b_ptr + (size_t)k0 * 256 + 4);
        }

        #pragma unroll
        for (int kk = 0; kk < 16; kk++) {
            float a[8], b[8];
            *(float4*)&a[0] = *(const float4*)&As[buf][kk][ty * 8];
            *(float4*)&a[4] = *(const float4*)&As[buf][kk][ty * 8 + 4];
            *(float4*)&b[0] = *(const float4*)&Bs[buf][kk][tx * 8];
            *(float4*)&b[4] = *(const float4*)&Bs[buf][kk][tx * 8 + 4];
            #pragma unroll
            for (int i = 0; i < 8; i++)
                #pragma unroll
                for (int j = 0; j < 8; j++)
                    acc[i][j] = fmaf(a[i], b[j], acc[i][j]);
        }

        if (t < 7) {
            const int nb = buf ^ 1;
            As[nb][a_cb + 0][a_row] = ra0.x;  As[nb][a_cb + 1][a_row] = ra0.y;
            As[nb][a_cb + 2][a_row] = ra0.z;  As[nb][a_cb + 3][a_row] = ra0.w;
            As[nb][a_cb + 4][a_row] = ra1.x;  As[nb][a_cb + 5][a_row] = ra1.y;
            As[nb][a_cb + 6][a_row] = ra1.z;  As[nb][a_cb + 7][a_row] = ra1.w;
            *(float4*)&Bs[nb][b_row][b_cb]     = rb0;
            *(float4*)&Bs[nb][b_row][b_cb + 4] = rb1;
        }
        __syncthreads();
        buf ^= 1;
    }

    // ---- epilogue: fold b1 for the U half (n0 < 256), write to g_uv ----
    const bool add_bias = (n0 < 256);
    #pragma unroll
    for (int i = 0; i < 8; i++) {
        const int row = m0 + ty * 8 + i;
        if (row >= M) continue;
        float* dst = g_uv + (size_t)row * 512 + n0 + tx * 8;
        #pragma unroll
        for (int jv = 0; jv < 2; jv++) {
            float4 c;
            c.x = acc[i][jv * 4 + 0];
            c.y = acc[i][jv * 4 + 1];
            c.z = acc[i][jv * 4 + 2];
            c.w = acc[i][jv * 4 + 3];
            if (add_bias) {
                const float* bb = b1 + n0 + tx * 8 + jv * 4;
                c.x += bb[0]; c.y += bb[1]; c.z += bb[2]; c.w += bb[3];
            }
            *(float4*)(dst + jv * 4) = c;
        }
    }
}

// ---------------------------------------------------------------------------
// Kernel 2: per-edge MLP tail.  One warp per edge.
//   raw = sum_j relu(U[row][j] + V[col][j]) * W2[j] + b2
//   out = (relu(raw) < 0.05) ? 0 : relu(raw)
// edge_index is INT32 [2, E] (harness converts int64 -> int32).
// Node indices clamped to the UV table range for IMA-safety.
// ---------------------------------------------------------------------------
__global__ __launch_bounds__(256)
void edge_mlp_kernel(const int* __restrict__ ei,
                     const float* __restrict__ W2,
                     const float* __restrict__ b2,
                     float* __restrict__ out, int E, int N)
{
    __shared__ float4 sW2[64];
    const int tid = threadIdx.x;
    if (tid < 64) sW2[tid] = ((const float4*)W2)[tid];
    __syncthreads();

    const int e = blockIdx.x * 8 + (tid >> 5);
    if (e >= E) return;
    const int lane = tid & 31;

    int r = ei[e];
    int c = ei[E + e];
    const int hi = N - 1;
    r = r < 0 ? 0 : (r > hi ? hi : r);
    c = c < 0 ? 0 : (c > hi ? hi : c);

    const float4* u4 = (const float4*)(g_uv + (size_t)r * 512);
    const float4* v4 = (const float4*)(g_uv + (size_t)c * 512 + 256);

    float acc = 0.f;
    #pragma unroll
    for (int i = 0; i < 2; i++) {
        const int j = lane + 32 * i;
        const float4 u = u4[j];
        const float4 v = v4[j];
        const float4 w = sW2[j];
        acc = fmaf(fmaxf(u.x + v.x, 0.f), w.x, acc);
        acc = fmaf(fmaxf(u.y + v.y, 0.f), w.y, acc);
        acc = fmaf(fmaxf(u.z + v.z, 0.f), w.z, acc);
        acc = fmaf(fmaxf(u.w + v.w, 0.f), w.w, acc);
    }

    #pragma unroll
    for (int off = 16; off; off >>= 1)
        acc += __shfl_xor_sync(0xFFFFFFFFu, acc, off);

    if (lane == 0) {
        float w = fmaxf(acc + b2[0], 0.f);
        out[e] = (w < 0.05f) ? 0.f : w;
    }
}

// ---------------------------------------------------------------------------
// Host: identify inputs BY ELEMENT COUNT:
//   emb = largest (N*128), edge_index = 2nd largest (2*E, int32),
//   W1 = 3rd largest (65536), b2 = smallest (1).
//   Remaining two 256-element inputs: R1's IMA is fully explained by the
//   int64->int32 conversion (packed garbage index, unclamped), so dict order
//   is back on the table: first-occurring = b1, second = W2.
// ---------------------------------------------------------------------------
extern "C" void kernel_launch(void* const* d_in, const int* in_sizes, int n_in,
                              void* d_out, int out_size)
{
    int ord[16];
    for (int i = 0; i < n_in; i++) ord[i] = i;
    for (int i = 0; i < n_in; i++)
        for (int j = i + 1; j < n_in; j++)
            if (in_sizes[ord[j]] > in_sizes[ord[i]]) { int t = ord[i]; ord[i] = ord[j]; ord[j] = t; }

    const int idx_emb = ord[0];
    const int idx_ei  = ord[1];
    const int idx_W1  = ord[2];
    const int idx_b2  = ord[n_in - 1];
    // remaining two, in original input order: first = b1, second = W2 (dict order)
    int idx_b1 = -1, idx_W2 = -1;
    for (int i = 0; i < n_in; i++) {
        if (i == idx_emb || i == idx_ei || i == idx_W1 || i == idx_b2) continue;
        if (idx_b1 < 0) idx_b1 = i; else idx_W2 = i;
    }

    const float* emb = (const float*)d_in[idx_emb];  // [N,128]
    const int*   ei  = (const int*)d_in[idx_ei];     // [2,E] int32
    const float* W1  = (const float*)d_in[idx_W1];   // [256,256]
    const float* b1  = (const float*)d_in[idx_b1];   // [256]
    const float* W2  = (const float*)d_in[idx_W2];   // [256,1]
    const float* b2  = (const float*)d_in[idx_b2];   // [1]
    float*       out = (float*)d_out;

    int N = in_sizes[idx_emb] / 128;
    if (N > UV_MAX_ROWS) N = UV_MAX_ROWS;       // never write scratch OOB
    const int E = in_sizes[idx_ei] / 2;

    // Phase 1: UV = emb @ [W1_top | W1_bot]  (+ b1 folded into U half)
    dim3 ggrid(4, (N + 127) / 128);
    uv_gemm_kernel<<<ggrid, 256>>>(emb, W1, b1, N);

    // Phase 2: per-edge gather + tail MLP
    const int blocks = (E + 7) / 8;
    edge_mlp_kernel<<<blocks, 256>>>(ei, W2, b2, out, E, N);
}

// round 6
// speedup vs baseline: 1.6632x; 1.6632x over previous
#include <cuda_runtime.h>
#include <cstdint>

// Scratch UV table: 512 floats per node (U = emb@W1_top + b1 in cols [0,256),
// V = emb@W1_bot in cols [256,512)). 131072 rows * 2KB = 268 MB.
#define UV_MAX_ROWS 131072
__device__ float g_uv[(size_t)UV_MAX_ROWS * 512];

// ---- packed f32x2 helpers (sm_103a FFMA2 path) ----
__device__ __forceinline__ void ffma2(unsigned long long& d,
                                      unsigned long long a,
                                      unsigned long long b)
{
    asm("fma.rn.f32x2 %0, %1, %2, %0;" : "+l"(d) : "l"(a), "l"(b));
}
__device__ __forceinline__ unsigned long long dup2(float x)
{
    unsigned long long r;
    asm("mov.b64 %0, {%1, %1};" : "=l"(r) : "f"(x));
    return r;
}

// ---------------------------------------------------------------------------
// Kernel 1: UV precompute GEMM.  C[M,512] = A[M,128] @ B[128,512] (+ b1 fold)
//   B[k, j]      = W1[k*256 + j]          for j <  256   (W1_top)
//   B[k, 256+j]  = W1[(128+k)*256 + j]    for j >= 256   (W1_bot)
// BM=128, BN=128, BK=16, 256 threads, 8x8/thread (split 4+4 rows/cols),
// double-buffered smem, packed fma.rn.f32x2 accumulation.
// ---------------------------------------------------------------------------
__global__ __launch_bounds__(256)
void uv_gemm_kernel(const float* __restrict__ A,
                    const float* __restrict__ W1,
                    const float* __restrict__ b1,
                    int M)
{
    __shared__ float As[2][16][128];   // [buf][k][m]  (A transposed)
    __shared__ float Bs[2][16][128];   // [buf][k][n]

    const int tid = threadIdx.x;
    const int m0  = blockIdx.y * 128;
    const int n0  = blockIdx.x * 128;          // 0,128,256,384
    const float* Wb  = W1 + (n0 >= 256 ? 128 * 256 : 0);
    const int    nc0 = n0 & 255;               // 0 or 128

    const int tx = tid & 15;                   // col group 0..15
    const int ty = tid >> 4;                   // row group 0..15

    // A-load: thread -> row (tid>>1), 8 floats at col (tid&1)*8
    const int a_row = tid >> 1;
    const int a_cb  = (tid & 1) * 8;
    const bool a_valid = (m0 + a_row) < M;
    const float* a_ptr = A + (size_t)(m0 + a_row) * 128 + a_cb;

    // B-load: thread -> row (tid>>4), 8 floats at col (tid&15)*8
    const int b_row = tid >> 4;
    const int b_cb  = (tid & 15) * 8;
    const float* b_ptr = Wb + (size_t)b_row * 256 + nc0 + b_cb;

    // acc2[i][j2]: i = row frag (0..3 -> ty*4+i, 4..7 -> 64+ty*4+i-4)
    //             j2 = col pair (0..1 -> tx*4+2*j2, 2..3 -> 64+tx*4+2*(j2-2))
    unsigned long long acc2[8][4];
    #pragma unroll
    for (int i = 0; i < 8; i++)
        #pragma unroll
        for (int j = 0; j < 4; j++) acc2[i][j] = 0ull;

    float4 ra0, ra1, rb0, rb1;
    const float4 z4 = make_float4(0.f, 0.f, 0.f, 0.f);

    // ---- prologue: k-tile 0 ----
    ra0 = a_valid ? *(const float4*)(a_ptr)     : z4;
    ra1 = a_valid ? *(const float4*)(a_ptr + 4) : z4;
    rb0 = *(const float4*)(b_ptr);
    rb1 = *(const float4*)(b_ptr + 4);

    As[0][a_cb + 0][a_row] = ra0.x;  As[0][a_cb + 1][a_row] = ra0.y;
    As[0][a_cb + 2][a_row] = ra0.z;  As[0][a_cb + 3][a_row] = ra0.w;
    As[0][a_cb + 4][a_row] = ra1.x;  As[0][a_cb + 5][a_row] = ra1.y;
    As[0][a_cb + 6][a_row] = ra1.z;  As[0][a_cb + 7][a_row] = ra1.w;
    *(float4*)&Bs[0][b_row][b_cb]     = rb0;
    *(float4*)&Bs[0][b_row][b_cb + 4] = rb1;
    __syncthreads();

    int buf = 0;
    #pragma unroll 1
    for (int t = 0; t < 8; t++) {           // 8 k-tiles of 16 (K=128)
        if (t < 7) {
            const int k0 = (t + 1) * 16;
            ra0 = a_valid ? *(const float4*)(a_ptr + k0)     : z4;
            ra1 = a_valid ? *(const float4*)(a_ptr + k0 + 4) : z4;
            rb0 = *(const float4*)(b_ptr + (size_t)k0 * 256);
            rb1 = *(const float4*)(b_ptr + (size_t)k0 * 256 + 4);
        }

        #pragma unroll
        for (int kk = 0; kk < 16; kk++) {
            // conflict-free fragment loads (16B lane stride)
            float4 af0 = *(const float4*)&As[buf][kk][ty * 4];
            float4 af1 = *(const float4*)&As[buf][kk][64 + ty * 4];
            float4 bf0 = *(const float4*)&Bs[buf][kk][tx * 4];
            float4 bf1 = *(const float4*)&Bs[buf][kk][64 + tx * 4];

            unsigned long long bp[4];
            bp[0] = *(unsigned long long*)&bf0.x;
            bp[1] = *(unsigned long long*)&bf0.z;
            bp[2] = *(unsigned long long*)&bf1.x;
            bp[3] = *(unsigned long long*)&bf1.z;

            unsigned long long ad[8];
            ad[0] = dup2(af0.x); ad[1] = dup2(af0.y);
            ad[2] = dup2(af0.z); ad[3] = dup2(af0.w);
            ad[4] = dup2(af1.x); ad[5] = dup2(af1.y);
            ad[6] = dup2(af1.z); ad[7] = dup2(af1.w);

            #pragma unroll
            for (int i = 0; i < 8; i++)
                #pragma unroll
                for (int j = 0; j < 4; j++)
                    ffma2(acc2[i][j], ad[i], bp[j]);
        }

        if (t < 7) {
            const int nb = buf ^ 1;
            As[nb][a_cb + 0][a_row] = ra0.x;  As[nb][a_cb + 1][a_row] = ra0.y;
            As[nb][a_cb + 2][a_row] = ra0.z;  As[nb][a_cb + 3][a_row] = ra0.w;
            As[nb][a_cb + 4][a_row] = ra1.x;  As[nb][a_cb + 5][a_row] = ra1.y;
            As[nb][a_cb + 6][a_row] = ra1.z;  As[nb][a_cb + 7][a_row] = ra1.w;
            *(float4*)&Bs[nb][b_row][b_cb]     = rb0;
            *(float4*)&Bs[nb][b_row][b_cb + 4] = rb1;
        }
        __syncthreads();
        buf ^= 1;
    }

    // ---- epilogue: fold b1 for U half (n0 < 256), write to g_uv ----
    const bool add_bias = (n0 < 256);
    const int c0 = n0 + tx * 4;
    const int c1 = n0 + 64 + tx * 4;
    float4 bb0 = z4, bb1 = z4;
    if (add_bias) {
        bb0 = *(const float4*)(b1 + (c0 - n0) + nc0 + (n0 < 256 ? n0 : 0));
        // (n0 < 256 means c0-n0+n0 = c0 indexes b1 directly)
        bb0 = *(const float4*)(b1 + c0);
        bb1 = *(const float4*)(b1 + c1);
    }

    #pragma unroll
    for (int i = 0; i < 8; i++) {
        const int row = m0 + (i < 4 ? ty * 4 + i : 64 + ty * 4 + (i - 4));
        if (row >= M) continue;
        float* dst = g_uv + (size_t)row * 512;

        union { unsigned long long u; float2 f; } p0, p1;
        float4 c;

        p0.u = acc2[i][0]; p1.u = acc2[i][1];
        c.x = p0.f.x + bb0.x; c.y = p0.f.y + bb0.y;
        c.z = p1.f.x + bb0.z; c.w = p1.f.y + bb0.w;
        *(float4*)(dst + c0) = c;

        p0.u = acc2[i][2]; p1.u = acc2[i][3];
        c.x = p0.f.x + bb1.x; c.y = p0.f.y + bb1.y;
        c.z = p1.f.x + bb1.z; c.w = p1.f.y + bb1.w;
        *(float4*)(dst + c1) = c;
    }
}

// ---------------------------------------------------------------------------
// Kernel 2: per-edge MLP tail.  One warp per edge.
//   raw = sum_j relu(U[row][j] + V[col][j]) * W2[j] + b2
//   out = (relu(raw) < 0.05) ? 0 : relu(raw)
// edge_index is INT32 [2, E]. Indices clamped for IMA-safety.
// ---------------------------------------------------------------------------
__global__ __launch_bounds__(256)
void edge_mlp_kernel(const int* __restrict__ ei,
                     const float* __restrict__ W2,
                     const float* __restrict__ b2,
                     float* __restrict__ out, int E, int N)
{
    __shared__ float4 sW2[64];
    const int tid = threadIdx.x;
    if (tid < 64) sW2[tid] = ((const float4*)W2)[tid];
    __syncthreads();

    const int e = blockIdx.x * 8 + (tid >> 5);
    if (e >= E) return;
    const int lane = tid & 31;

    int r = ei[e];
    int c = ei[E + e];
    const int hi = N - 1;
    r = r < 0 ? 0 : (r > hi ? hi : r);
    c = c < 0 ? 0 : (c > hi ? hi : c);

    const float4* u4 = (const float4*)(g_uv + (size_t)r * 512);
    const float4* v4 = (const float4*)(g_uv + (size_t)c * 512 + 256);

    float acc = 0.f;
    #pragma unroll
    for (int i = 0; i < 2; i++) {
        const int j = lane + 32 * i;
        const float4 u = u4[j];
        const float4 v = v4[j];
        const float4 w = sW2[j];
        acc = fmaf(fmaxf(u.x + v.x, 0.f), w.x, acc);
        acc = fmaf(fmaxf(u.y + v.y, 0.f), w.y, acc);
        acc = fmaf(fmaxf(u.z + v.z, 0.f), w.z, acc);
        acc = fmaf(fmaxf(u.w + v.w, 0.f), w.w, acc);
    }

    #pragma unroll
    for (int off = 16; off; off >>= 1)
        acc += __shfl_xor_sync(0xFFFFFFFFu, acc, off);

    if (lane == 0) {
        float w = fmaxf(acc + b2[0], 0.f);
        out[e] = (w < 0.05f) ? 0.f : w;
    }
}

// ---------------------------------------------------------------------------
// Host: identify inputs BY ELEMENT COUNT (proven mapping from R5):
//   emb = largest, edge_index = 2nd largest (int32), W1 = 3rd, b2 = smallest,
//   remaining two 256-elem in original order: first = b1, second = W2.
// ---------------------------------------------------------------------------
extern "C" void kernel_launch(void* const* d_in, const int* in_sizes, int n_in,
                              void* d_out, int out_size)
{
    int ord[16];
    for (int i = 0; i < n_in; i++) ord[i] = i;
    for (int i = 0; i < n_in; i++)
        for (int j = i + 1; j < n_in; j++)
            if (in_sizes[ord[j]] > in_sizes[ord[i]]) { int t = ord[i]; ord[i] = ord[j]; ord[j] = t; }

    const int idx_emb = ord[0];
    const int idx_ei  = ord[1];
    const int idx_W1  = ord[2];
    const int idx_b2  = ord[n_in - 1];
    int idx_b1 = -1, idx_W2 = -1;
    for (int i = 0; i < n_in; i++) {
        if (i == idx_emb || i == idx_ei || i == idx_W1 || i == idx_b2) continue;
        if (idx_b1 < 0) idx_b1 = i; else idx_W2 = i;
    }

    const float* emb = (const float*)d_in[idx_emb];  // [N,128]
    const int*   ei  = (const int*)d_in[idx_ei];     // [2,E] int32
    const float* W1  = (const float*)d_in[idx_W1];   // [256,256]
    const float* b1  = (const float*)d_in[idx_b1];   // [256]
    const float* W2  = (const float*)d_in[idx_W2];   // [256,1]
    const float* b2  = (const float*)d_in[idx_b2];   // [1]
    float*       out = (float*)d_out;

    int N = in_sizes[idx_emb] / 128;
    if (N > UV_MAX_ROWS) N = UV_MAX_ROWS;
    const int E = in_sizes[idx_ei] / 2;

    dim3 ggrid(4, (N + 127) / 128);
    uv_gemm_kernel<<<ggrid, 256>>>(emb, W1, b1, N);

    const int blocks = (E + 7) / 8;
    edge_mlp_kernel<<<blocks, 256>>>(ei, W2, b2, out, E, N);
}